// round 17
// baseline (speedup 1.0000x reference)
#include <cuda_runtime.h>
#include <cuda_bf16.h>
#include <cstdint>

// ---------------- problem constants ----------------
#define NN   4096
#define HH   128
#define BB   64
#define E0C  131072
#define NEC  135168
#define KKC  52
#define NKC  3328
#define NSLOPE 0.01f

// output layout (floats)
#define OFF_XOUT 0
#define OFF_A2   (NKC*HH)
#define OFF_BATCH (OFF_A2 + (size_t)NKC*NKC)
#define OFF_PERM  (OFF_BATCH + NKC)

// ---------------- scratch layout ----------------
constexpr size_t O_DEG  = 0;                               // NN (zeroed)
constexpr size_t O_AT   = (size_t)NN;                      // 64*4096 raw sums (zeroed)
constexpr size_t O_CNTT = O_AT + (size_t)64*4096;          // 64*4096 (zeroed)
constexpr size_t O_ST   = O_CNTT + (size_t)64*4096;        // 64*4096
constexpr size_t O_H3   = O_ST + (size_t)64*4096;          // 2*NN*384
constexpr size_t O_T1   = O_H3 + (size_t)2*NN*384;         // 2*NN*256
constexpr size_t O_LP   = O_T1 + (size_t)2*NN*256;         // 4*NN logit partials
constexpr size_t O_XQ   = O_LP + (size_t)4*NN;
constexpr size_t O_AGG  = O_XQ + (size_t)NN*128;
constexpr size_t O_G0   = O_AGG + (size_t)NN*128;          // 2*NN*128
constexpr size_t O_XC   = O_G0 + (size_t)2*NN*128;
constexpr size_t O_XQ2  = O_XC + (size_t)NN*128;
constexpr size_t O_PERM = O_XQ2 + (size_t)NN*128;          // NKC ints
constexpr size_t O_W1E  = O_PERM + NKC;                    // 4*384*256
constexpr size_t SCRATCH_ELEMS = O_W1E + (size_t)4*384*256;

__device__ __align__(16) float d_scratch[SCRATCH_ELEMS];

__device__ __forceinline__ float lrelu(float v){ return v >= 0.f ? v : NSLOPE*v; }

// packed fp32x2 fma (Blackwell)
#define FMA2(accv, av, bv) \
    asm("fma.rn.f32x2 %0, %1, %2, %3;" : "=l"(accv) : "l"(av), "l"(bv), "l"(accv))

union UF2 { unsigned long long u; float2 f; };

// ---------------- prep0: zero deg+AT+CNT (float4), build folded W1 ----------------
__global__ void prep0(float4* zbase4, const float* __restrict__ W1, float* __restrict__ W1e){
    int b = blockIdx.x;
    const int ZN4 = (NN + 2*64*4096) / 4;
    if (b < 32){
        float4 z = make_float4(0.f,0.f,0.f,0.f);
        for (int i = b*256 + threadIdx.x; i < ZN4; i += 32*256) zbase4[i] = z;
        return;
    }
    int idx = (b-32)*256 + threadIdx.x;
    if (idx >= 4*384*256) return;
    int h = idx / (384*256);
    int rem = idx - h*(384*256);
    int r = rem >> 8, c = rem & 255;
    const float* Wh = W1 + (size_t)h*512*256;
    float v;
    if (r < 128)       v = Wh[(size_t)r*256 + c] + Wh[(size_t)(256+r)*256 + c];
    else if (r < 256)  v = Wh[(size_t)r*256 + c] - Wh[(size_t)(r+128)*256 + c];
    else               v = Wh[(size_t)(r+128)*256 + c];
    W1e[idx] = v;
}

// ---------------- single edge pass: deg + raw AT + CNT ----------------
__global__ void edge_build(const int* __restrict__ ei, const float* __restrict__ w,
                           float* __restrict__ deg, float* __restrict__ AT,
                           float* __restrict__ CNT){
    int e = blockIdx.x*blockDim.x + threadIdx.x;
    if (e >= NEC) return;
    int r, c; float wv;
    if (e < E0C){ r = ei[e]; c = ei[E0C + e]; wv = w[e]; }
    else        { r = c = e - E0C; wv = 1.f; }
    atomicAdd(&deg[c], wv);
    int idx = (r >> 6)*4096 + (c & 63)*64 + (r & 63);
    atomicAdd(&AT[idx], wv);
    atomicAdd(&CNT[idx], 1.f);
}

// ---------------- double hop, dense per graph: out = A^T (A^T in), dinv folded ----------------
__global__ __launch_bounds__(256) void hop2_dense(const float* __restrict__ xin,
                                                  float* __restrict__ xout,
                                                  const float* __restrict__ AT,
                                                  const float* __restrict__ deg){
    extern __shared__ float sm[];
    float* sA = sm;              // 64*65
    float* sX = sm + 4160;       // 64*132
    float* sY = sX + 8448;       // 64*132
    float* sD = sY + 8448;       // 64
    int b = blockIdx.x, tid = threadIdx.x;
    for (int i = tid; i < 4096; i += 256)
        sA[(i>>6)*65 + (i&63)] = AT[(size_t)b*4096 + i];
    for (int i = tid; i < 8192; i += 256){
        int r = i >> 7, h = i & 127;
        sX[r*132 + h] = xin[(size_t)(b*64+r)*128 + h];
    }
    if (tid < 64) sD[tid] = rsqrtf(fmaxf(deg[b*64 + tid], 1e-12f));
    __syncthreads();
    for (int i = tid; i < 4096; i += 256){
        int c = i >> 6, r = i & 63;
        sA[c*65 + r] *= sD[r]*sD[c];
    }
    __syncthreads();
    const int tc = tid >> 5;
    const int th = (tid & 31) << 2;
    {
        unsigned long long acc[8][2];
        #pragma unroll
        for (int cc = 0; cc < 8; cc++){ acc[cc][0]=0ull; acc[cc][1]=0ull; }
        for (int r = 0; r < 64; r++){
            ulonglong2 xv = *(const ulonglong2*)&sX[r*132 + th];
            #pragma unroll
            for (int cc = 0; cc < 8; cc++){
                UF2 ap; float a = sA[(tc*8+cc)*65 + r];
                ap.f = make_float2(a, a);
                FMA2(acc[cc][0], ap.u, xv.x);
                FMA2(acc[cc][1], ap.u, xv.y);
            }
        }
        #pragma unroll
        for (int cc = 0; cc < 8; cc++){
            ulonglong2 o; o.x = acc[cc][0]; o.y = acc[cc][1];
            *(ulonglong2*)&sY[(tc*8+cc)*132 + th] = o;
        }
    }
    __syncthreads();
    {
        unsigned long long acc[8][2];
        #pragma unroll
        for (int cc = 0; cc < 8; cc++){ acc[cc][0]=0ull; acc[cc][1]=0ull; }
        for (int r = 0; r < 64; r++){
            ulonglong2 xv = *(const ulonglong2*)&sY[r*132 + th];
            #pragma unroll
            for (int cc = 0; cc < 8; cc++){
                UF2 ap; float a = sA[(tc*8+cc)*65 + r];
                ap.f = make_float2(a, a);
                FMA2(acc[cc][0], ap.u, xv.x);
                FMA2(acc[cc][1], ap.u, xv.y);
            }
        }
        #pragma unroll
        for (int cc = 0; cc < 8; cc++){
            ulonglong2 o; o.x = acc[cc][0]; o.y = acc[cc][1];
            *(ulonglong2*)&xout[(size_t)(b*64 + tc*8+cc)*128 + th] = o;
        }
    }
}

// ---------------- double-buffered packed fp32x2 GEMM (64x64 tile, z-batched) ----------------
__global__ __launch_bounds__(256) void gemm64p(
        const float* __restrict__ A, const float* __restrict__ B,
        float* __restrict__ C, int N, int K, int leaky,
        size_t Astr, size_t Bstr, size_t Cstr){
    A += blockIdx.z*Astr; B += blockIdx.z*Bstr; C += blockIdx.z*Cstr;
    __shared__ __align__(16) float AsD[2][16*136];
    __shared__ __align__(16) float Bs[2][16*68];
    const int tid = threadIdx.x;
    const int tn = tid & 15;
    const int tm = tid >> 4;
    const int row0 = blockIdx.y*64;
    const int col0 = blockIdx.x*64;
    const int arow = tid >> 2;
    const int acol = (tid & 3) << 2;
    const int brow = tid >> 4;
    const int bcol = (tid & 15) << 2;
    const float* Ap = A + (size_t)(row0+arow)*K + acol;
    const float* Bp = B + (size_t)brow*N + col0 + bcol;
    unsigned long long acc[4][2];
    #pragma unroll
    for (int i = 0; i < 4; i++){ acc[i][0] = 0ull; acc[i][1] = 0ull; }
    const int nk = K >> 4;
    float4 av = *(const float4*)Ap;
    float4 bv = *(const float4*)Bp;
    {
        float* Ad = AsD[0];
        *(float2*)&Ad[(acol+0)*136 + 2*arow] = make_float2(av.x, av.x);
        *(float2*)&Ad[(acol+1)*136 + 2*arow] = make_float2(av.y, av.y);
        *(float2*)&Ad[(acol+2)*136 + 2*arow] = make_float2(av.z, av.z);
        *(float2*)&Ad[(acol+3)*136 + 2*arow] = make_float2(av.w, av.w);
        *(float4*)&Bs[0][brow*68 + bcol] = bv;
    }
    __syncthreads();
    for (int t = 0; t < nk; t++){
        int cur = t & 1;
        if (t+1 < nk){
            av = *(const float4*)(Ap + (t+1)*16);
            bv = *(const float4*)(Bp + (size_t)(t+1)*16*N);
        }
        const float* Ad = AsD[cur];
        const float* Bb = Bs[cur];
        #pragma unroll
        for (int k = 0; k < 16; k++){
            ulonglong2 aD0 = *reinterpret_cast<const ulonglong2*>(&Ad[k*136 + tm*8]);
            ulonglong2 aD1 = *reinterpret_cast<const ulonglong2*>(&Ad[k*136 + tm*8 + 4]);
            ulonglong2 bp  = *reinterpret_cast<const ulonglong2*>(&Bb[k*68 + tn*4]);
            FMA2(acc[0][0], aD0.x, bp.x); FMA2(acc[0][1], aD0.x, bp.y);
            FMA2(acc[1][0], aD0.y, bp.x); FMA2(acc[1][1], aD0.y, bp.y);
            FMA2(acc[2][0], aD1.x, bp.x); FMA2(acc[2][1], aD1.x, bp.y);
            FMA2(acc[3][0], aD1.y, bp.x); FMA2(acc[3][1], aD1.y, bp.y);
        }
        if (t+1 < nk){
            float* Ad2 = AsD[cur^1];
            *(float2*)&Ad2[(acol+0)*136 + 2*arow] = make_float2(av.x, av.x);
            *(float2*)&Ad2[(acol+1)*136 + 2*arow] = make_float2(av.y, av.y);
            *(float2*)&Ad2[(acol+2)*136 + 2*arow] = make_float2(av.z, av.z);
            *(float2*)&Ad2[(acol+3)*136 + 2*arow] = make_float2(av.w, av.w);
            *(float4*)&Bs[cur^1][brow*68 + bcol] = bv;
        }
        __syncthreads();
    }
    #pragma unroll
    for (int i = 0; i < 4; i++){
        int r = row0 + (tm<<2) + i;
        #pragma unroll
        for (int jp = 0; jp < 2; jp++){
            UF2 cv; cv.u = acc[i][jp];
            float2 v = cv.f;
            if (leaky){
                v.x = v.x >= 0.f ? v.x : NSLOPE*v.x;
                v.y = v.y >= 0.f ? v.y : NSLOPE*v.y;
            }
            *(float2*)(C + (size_t)r*N + col0 + (tn<<2) + jp*2) = v;
        }
    }
}

// ---------------- Wk GEMM with fused h3 epilogue ----------------
__global__ __launch_bounds__(256) void gemm_h3(
        const float* __restrict__ kv, const float* __restrict__ Wk,
        const float* __restrict__ q0, const float* __restrict__ tx,
        float* __restrict__ h3){
    const int head = blockIdx.z;
    const float* B = Wk + (size_t)head*128*128;
    __shared__ __align__(16) float AsD[2][16*136];
    __shared__ __align__(16) float Bs[2][16*68];
    const int tid = threadIdx.x;
    const int tn = tid & 15;
    const int tm = tid >> 4;
    const int row0 = blockIdx.y*64;
    const int col0 = blockIdx.x*64;
    const int arow = tid >> 2;
    const int acol = (tid & 3) << 2;
    const int brow = tid >> 4;
    const int bcol = (tid & 15) << 2;
    const float* Ap = kv + (size_t)(row0+arow)*128 + acol;
    const float* Bp = B + (size_t)brow*128 + col0 + bcol;
    unsigned long long acc[4][2];
    #pragma unroll
    for (int i = 0; i < 4; i++){ acc[i][0] = 0ull; acc[i][1] = 0ull; }
    float4 av = *(const float4*)Ap;
    float4 bv = *(const float4*)Bp;
    {
        float* Ad = AsD[0];
        *(float2*)&Ad[(acol+0)*136 + 2*arow] = make_float2(av.x, av.x);
        *(float2*)&Ad[(acol+1)*136 + 2*arow] = make_float2(av.y, av.y);
        *(float2*)&Ad[(acol+2)*136 + 2*arow] = make_float2(av.z, av.z);
        *(float2*)&Ad[(acol+3)*136 + 2*arow] = make_float2(av.w, av.w);
        *(float4*)&Bs[0][brow*68 + bcol] = bv;
    }
    __syncthreads();
    #pragma unroll 1
    for (int t = 0; t < 8; t++){
        int cur = t & 1;
        if (t < 7){
            av = *(const float4*)(Ap + (t+1)*16);
            bv = *(const float4*)(Bp + (size_t)(t+1)*16*128);
        }
        const float* Ad = AsD[cur];
        const float* Bb = Bs[cur];
        #pragma unroll
        for (int k = 0; k < 16; k++){
            ulonglong2 aD0 = *reinterpret_cast<const ulonglong2*>(&Ad[k*136 + tm*8]);
            ulonglong2 aD1 = *reinterpret_cast<const ulonglong2*>(&Ad[k*136 + tm*8 + 4]);
            ulonglong2 bp  = *reinterpret_cast<const ulonglong2*>(&Bb[k*68 + tn*4]);
            FMA2(acc[0][0], aD0.x, bp.x); FMA2(acc[0][1], aD0.x, bp.y);
            FMA2(acc[1][0], aD0.y, bp.x); FMA2(acc[1][1], aD0.y, bp.y);
            FMA2(acc[2][0], aD1.x, bp.x); FMA2(acc[2][1], aD1.x, bp.y);
            FMA2(acc[3][0], aD1.y, bp.x); FMA2(acc[3][1], aD1.y, bp.y);
        }
        if (t < 7){
            float* Ad2 = AsD[cur^1];
            *(float2*)&Ad2[(acol+0)*136 + 2*arow] = make_float2(av.x, av.x);
            *(float2*)&Ad2[(acol+1)*136 + 2*arow] = make_float2(av.y, av.y);
            *(float2*)&Ad2[(acol+2)*136 + 2*arow] = make_float2(av.z, av.z);
            *(float2*)&Ad2[(acol+3)*136 + 2*arow] = make_float2(av.w, av.w);
            *(float4*)&Bs[cur^1][brow*68 + bcol] = bv;
        }
        __syncthreads();
    }
    float* h3h = h3 + (size_t)head*NN*384;
    #pragma unroll
    for (int i = 0; i < 4; i++){
        int r = row0 + (tm<<2) + i;
        float* hr = h3h + (size_t)r*384;
        #pragma unroll
        for (int jp = 0; jp < 2; jp++){
            UF2 cv; cv.u = acc[i][jp];
            int col = col0 + (tn<<2) + jp*2;
            float2 q = head ? *(const float2*)(tx + (size_t)(r>>6)*128 + col)
                            : *(const float2*)(q0 + (size_t)r*128 + col);
            *(float2*)(hr + col)       = cv.f;
            *(float2*)(hr + 128 + col) = q;
            *(float2*)(hr + 256 + col) = make_float2(cv.f.x*q.x, cv.f.y*q.y);
        }
    }
}

// ---------------- W2 GEMM with fused W3 dot epilogue → logit partials ----------------
// lp[head*2*NN + colblk*NN + row] = sum over this col-tile of lrelu(t2[row][c]) * W3[c]
__global__ __launch_bounds__(256) void gemm_w2tail(
        const float* __restrict__ t1, const float* __restrict__ W2,
        const float* __restrict__ W3, float* __restrict__ lp){
    const int head = blockIdx.z;
    const float* A = t1 + (size_t)head*NN*256;
    const float* B = W2 + (size_t)head*256*128;
    __shared__ __align__(16) float AsD[2][16*136];
    __shared__ __align__(16) float Bs[2][16*68];
    const int tid = threadIdx.x;
    const int tn = tid & 15;
    const int tm = tid >> 4;
    const int row0 = blockIdx.y*64;
    const int col0 = blockIdx.x*64;
    const int arow = tid >> 2;
    const int acol = (tid & 3) << 2;
    const int brow = tid >> 4;
    const int bcol = (tid & 15) << 2;
    const float* Ap = A + (size_t)(row0+arow)*256 + acol;
    const float* Bp = B + (size_t)brow*128 + col0 + bcol;
    unsigned long long acc[4][2];
    #pragma unroll
    for (int i = 0; i < 4; i++){ acc[i][0] = 0ull; acc[i][1] = 0ull; }
    float4 av = *(const float4*)Ap;
    float4 bv = *(const float4*)Bp;
    {
        float* Ad = AsD[0];
        *(float2*)&Ad[(acol+0)*136 + 2*arow] = make_float2(av.x, av.x);
        *(float2*)&Ad[(acol+1)*136 + 2*arow] = make_float2(av.y, av.y);
        *(float2*)&Ad[(acol+2)*136 + 2*arow] = make_float2(av.z, av.z);
        *(float2*)&Ad[(acol+3)*136 + 2*arow] = make_float2(av.w, av.w);
        *(float4*)&Bs[0][brow*68 + bcol] = bv;
    }
    __syncthreads();
    #pragma unroll 1
    for (int t = 0; t < 16; t++){
        int cur = t & 1;
        if (t < 15){
            av = *(const float4*)(Ap + (t+1)*16);
            bv = *(const float4*)(Bp + (size_t)(t+1)*16*128);
        }
        const float* Ad = AsD[cur];
        const float* Bb = Bs[cur];
        #pragma unroll
        for (int k = 0; k < 16; k++){
            ulonglong2 aD0 = *reinterpret_cast<const ulonglong2*>(&Ad[k*136 + tm*8]);
            ulonglong2 aD1 = *reinterpret_cast<const ulonglong2*>(&Ad[k*136 + tm*8 + 4]);
            ulonglong2 bp  = *reinterpret_cast<const ulonglong2*>(&Bb[k*68 + tn*4]);
            FMA2(acc[0][0], aD0.x, bp.x); FMA2(acc[0][1], aD0.x, bp.y);
            FMA2(acc[1][0], aD0.y, bp.x); FMA2(acc[1][1], aD0.y, bp.y);
            FMA2(acc[2][0], aD1.x, bp.x); FMA2(acc[2][1], aD1.x, bp.y);
            FMA2(acc[3][0], aD1.y, bp.x); FMA2(acc[3][1], aD1.y, bp.y);
        }
        if (t < 15){
            float* Ad2 = AsD[cur^1];
            *(float2*)&Ad2[(acol+0)*136 + 2*arow] = make_float2(av.x, av.x);
            *(float2*)&Ad2[(acol+1)*136 + 2*arow] = make_float2(av.y, av.y);
            *(float2*)&Ad2[(acol+2)*136 + 2*arow] = make_float2(av.z, av.z);
            *(float2*)&Ad2[(acol+3)*136 + 2*arow] = make_float2(av.w, av.w);
            *(float4*)&Bs[cur^1][brow*68 + bcol] = bv;
        }
        __syncthreads();
    }
    // epilogue: partial dot with W3 over this col tile
    const float* W3h = W3 + (size_t)head*128 + col0 + (tn<<2);
    float w30 = W3h[0], w31 = W3h[1], w32 = W3h[2], w33 = W3h[3];
    #pragma unroll
    for (int i = 0; i < 4; i++){
        UF2 c0, c1; c0.u = acc[i][0]; c1.u = acc[i][1];
        float p = lrelu(c0.f.x)*w30 + lrelu(c0.f.y)*w31
                + lrelu(c1.f.x)*w32 + lrelu(c1.f.y)*w33;
        #pragma unroll
        for (int o = 8; o; o >>= 1) p += __shfl_xor_sync(0xffffffffu, p, o, 16);
        if (tn == 0){
            int row = row0 + (tm<<2) + i;
            lp[(size_t)head*2*NN + (size_t)blockIdx.x*NN + row] = p;
        }
    }
}

// ---------------- dense edge softmax + per-head node softmax + agg = S^T X ----------------
__global__ __launch_bounds__(256) void esm_agg(const float* __restrict__ CNT,
                                               const float* __restrict__ lp,
                                               const float* __restrict__ x,
                                               float* __restrict__ STg,
                                               float* __restrict__ agg){
    extern __shared__ float sm[];
    float* sCT = sm;             // 4160
    float* sST = sm + 4160;      // 4160
    float* sX  = sm + 8320;      // 8448
    float* sL  = sm + 16768;     // 128 (→ becomes softmaxed f1|f2)
    float* sE  = sm + 16896;     // 128
    int b = blockIdx.x, tid = threadIdx.x;
    for (int i = tid; i < 4096; i += 256)
        sCT[(i>>6)*65 + (i&63)] = CNT[(size_t)b*4096 + i];
    for (int i = tid; i < 8192; i += 256){
        int r = i >> 7, h = i & 127;
        sX[r*132 + h] = x[(size_t)(b*64+r)*128 + h];
    }
    if (tid < 128){
        int head = tid >> 6, t = tid & 63;
        const float* lph = lp + (size_t)head*2*NN;
        int i = b*64 + t;
        sL[tid] = lrelu(lph[i] + lph[NN + i]);
    }
    __syncthreads();
    float ev = 0.f;
    if (tid < 128){
        int base = tid & 64;
        float m = -1e30f;
        #pragma unroll 8
        for (int j = 0; j < 64; j++) m = fmaxf(m, sL[base + j]);
        ev = expf(sL[tid] - m);
        sE[tid] = ev;
    }
    __syncthreads();
    if (tid < 128){
        int base = tid & 64;
        float s = 0.f;
        #pragma unroll 8
        for (int j = 0; j < 64; j++) s += sE[base + j];
        sE[tid] = ev / s;     // temporarily in sE
    }
    __syncthreads();
    if (tid < 128) sL[tid] = sE[tid];   // sL[0..63]=f1, sL[64..127]=f2
    __syncthreads();
    if (tid < 64){
        int c = tid; float f1c = sL[c];
        float m = -1e30f;
        for (int r = 0; r < 64; r++)
            if (sCT[c*65+r] > 0.5f)
                m = fmaxf(m, lrelu(f1c + sL[64+r]));
        float den = 0.f;
        for (int r = 0; r < 64; r++){
            float cv = sCT[c*65+r];
            float e2 = 0.f;
            if (cv > 0.5f){
                e2 = cv * expf(lrelu(f1c + sL[64+r]) - m);
                den += e2;
            }
            sST[c*65+r] = e2;
        }
        float inv = 1.f / den;
        for (int r = 0; r < 64; r++) sST[c*65+r] *= inv;
    }
    __syncthreads();
    for (int i = tid; i < 4096; i += 256)
        STg[(size_t)b*4096 + i] = sST[(i>>6)*65 + (i&63)];
    const int tc = tid >> 5;
    const int th = (tid & 31) << 2;
    unsigned long long acc[8][2];
    #pragma unroll
    for (int cc = 0; cc < 8; cc++){ acc[cc][0]=0ull; acc[cc][1]=0ull; }
    for (int r = 0; r < 64; r++){
        ulonglong2 xv = *(const ulonglong2*)&sX[r*132 + th];
        #pragma unroll
        for (int cc = 0; cc < 8; cc++){
            UF2 ap; float a = sST[(tc*8+cc)*65 + r];
            ap.f = make_float2(a, a);
            FMA2(acc[cc][0], ap.u, xv.x);
            FMA2(acc[cc][1], ap.u, xv.y);
        }
    }
    #pragma unroll
    for (int cc = 0; cc < 8; cc++){
        ulonglong2 o; o.x = acc[cc][0]; o.y = acc[cc][1];
        *(ulonglong2*)&agg[(size_t)(b*64 + tc*8+cc)*128 + th] = o;
    }
}
__global__ void xc_combine(const float* __restrict__ x, const float* __restrict__ g0,
                           const float* __restrict__ g1, float* __restrict__ xc){
    int idx = blockIdx.x*blockDim.x + threadIdx.x;
    if (idx >= NN*HH) return;
    float xv = x[idx];
    xc[idx] = 0.5f * (lrelu(xv + g0[idx]) + lrelu(xv + g1[idx]));
}

// ---------------- finalize: per-head softmax + score softmax + top-k + outputs ----------------
__global__ void finalize(const float* __restrict__ lp, const float* __restrict__ x,
                         int* __restrict__ perm, float* __restrict__ out){
    __shared__ float sL[128], sE[128], sv[64], se[64], ssc[64];
    __shared__ int sperm[KKC];
    int b = blockIdx.x, tid = threadIdx.x;
    if (tid < 128){
        int head = tid >> 6, t = tid & 63;
        const float* lph = lp + (size_t)head*2*NN;
        int i = b*64 + t;
        sL[tid] = lrelu(lph[i] + lph[NN + i]);
    }
    __syncthreads();
    float ev = 0.f;
    if (tid < 128){
        int base = tid & 64;
        float m = -1e30f;
        #pragma unroll 8
        for (int j = 0; j < 64; j++) m = fmaxf(m, sL[base + j]);
        ev = expf(sL[tid] - m);
        sE[tid] = ev;
    }
    __syncthreads();
    float fv = 0.f;
    if (tid < 128){
        int base = tid & 64;
        float s = 0.f;
        #pragma unroll 8
        for (int j = 0; j < 64; j++) s += sE[base + j];
        fv = ev / s;
    }
    __syncthreads();
    if (tid < 128) sE[tid] = fv;
    __syncthreads();
    float v = 0.f, e = 0.f;
    if (tid < 64){
        v = sE[tid] + sE[64 + tid];
        sv[tid] = v;
    }
    __syncthreads();
    if (tid < 64){
        float m = -1e30f;
        #pragma unroll 8
        for (int j = 0; j < 64; j++) m = fmaxf(m, sv[j]);
        e = expf(v - m);
        se[tid] = e;
    }
    __syncthreads();
    if (tid < 64){
        float s = 0.f;
        #pragma unroll 8
        for (int j = 0; j < 64; j++) s += se[j];
        float sc = e / s;
        ssc[tid] = sc;
        int rank = 0;
        for (int j = 0; j < 64; j++){
            float vj = sv[j];
            if (vj > v || (vj == v && j < tid)) rank++;
        }
        if (rank < KKC){
            int p = b*KKC + rank;
            sperm[rank] = tid;
            perm[p] = b*64 + tid;
            out[OFF_BATCH + p] = (float)b;
            out[OFF_PERM  + p] = (float)(b*64 + tid);
        }
    }
    __syncthreads();
    for (int idx = tid; idx < KKC*128; idx += blockDim.x){
        int p = idx >> 7, c = idx & 127;
        int node = sperm[p];
        out[OFF_XOUT + ((size_t)b*KKC + p)*128 + c] =
            x[(size_t)(b*64 + node)*128 + c] * ssc[node];
    }
}

// ---------------- dense triple product + direct full-row A2 write ----------------
__global__ __launch_bounds__(256) void a2_dense(const float* __restrict__ AT,
                                                const float* __restrict__ deg,
                                                const float* __restrict__ STg,
                                                const int* __restrict__ perm,
                                                float* __restrict__ outA2){
    extern __shared__ float sm[];
    float* sA = sm;              // 4160
    float* sS = sm + 4160;       // 4160
    float* sT = sm + 8320;       // 64*53 = 3392
    float* sU = sm + 11712;      // 52*53 = 2756
    float* sD = sm + 14468;      // 64
    int*   sp = (int*)(sm + 14532); // 52
    int b = blockIdx.x, tid = threadIdx.x;
    for (int i = tid; i < 4096; i += 256){
        int o = (i>>6)*65 + (i&63);
        sA[o] = AT[(size_t)b*4096 + i];
        sS[o] = STg[(size_t)b*4096 + i];
    }
    if (tid < 64) sD[tid] = rsqrtf(fmaxf(deg[b*64 + tid], 1e-12f));
    if (tid >= 64 && tid < 64 + KKC) sp[tid-64] = perm[b*KKC + tid - 64] & 63;
    __syncthreads();
    for (int i = tid; i < 4096; i += 256){
        int c = i >> 6, r = i & 63;
        sA[c*65 + r] *= sD[r]*sD[c];
    }
    __syncthreads();
    // T[r][j] = sum_k A[r][k]*S[k][pj] = sum_k sA[k][r]*sS[pj][k]
    {
        int r = tid & 63;
        for (int j = tid >> 6; j < KKC; j += 4){
            int pj = sp[j];
            float acc = 0.f;
            for (int k = 0; k < 64; k++)
                acc = fmaf(sA[k*65 + r], sS[pj*65 + k], acc);
            sT[r*53 + j] = acc;
        }
    }
    __syncthreads();
    // U[i][j] = sum_r S[r][pi]*T[r][j] = sum_r sS[pi][r]*T[r][j]
    {
        int i = tid & 63;
        if (i < KKC){
            int pi = sp[i];
            for (int j = tid >> 6; j < KKC; j += 4){
                float acc = 0.f;
                for (int r = 0; r < 64; r++)
                    acc = fmaf(sS[pi*65 + r], sT[r*53 + j], acc);
                sU[i*53 + j] = acc;
            }
        }
    }
    __syncthreads();
    // write 52 full A2 rows: zeros except band [b*52, b*52+52), diag = 1
    float4* out4 = (float4*)outA2;
    const int ROW4 = NKC/4;              // 832
    const int band0 = b*13;              // band start in float4 units
    for (int idx = tid; idx < KKC*ROW4; idx += 256){
        int i = idx / ROW4;
        int f = idx - i*ROW4;
        float4 v = make_float4(0.f,0.f,0.f,0.f);
        int fb = f - band0;
        if ((unsigned)fb < 13u){
            int cb = fb*4;
            v.x = sU[i*53 + cb];
            v.y = sU[i*53 + cb + 1];
            v.z = sU[i*53 + cb + 2];
            v.w = sU[i*53 + cb + 3];
            if (cb   == i) v.x = 1.f;
            if (cb+1 == i) v.y = 1.f;
            if (cb+2 == i) v.z = 1.f;
            if (cb+3 == i) v.w = 1.f;
        }
        out4[(size_t)(b*KKC + i)*ROW4 + f] = v;
    }
}

// ---------------- host launcher ----------------
extern "C" void kernel_launch(void* const* d_in, const int* in_sizes, int n_in,
                              void* d_out, int out_size){
    const float* x    = (const float*)d_in[0];
    const int*   ei   = (const int*)  d_in[1];
    const float* ewt  = (const float*)d_in[2];
    const float* tx   = (const float*)d_in[3];
    const float* Wk   = (const float*)d_in[5];
    const float* W1   = (const float*)d_in[6];
    const float* W2   = (const float*)d_in[7];
    const float* W3   = (const float*)d_in[8];
    const float* linW = (const float*)d_in[9];
    float* out = (float*)d_out;

    void* basep = nullptr;
    cudaGetSymbolAddress(&basep, d_scratch);
    float* base = (float*)basep;

    float* deg   = base + O_DEG;
    float* AT    = base + O_AT;
    float* CNT   = base + O_CNTT;
    float* STg   = base + O_ST;
    float* h3    = base + O_H3;
    float* t1    = base + O_T1;
    float* lp    = base + O_LP;
    float* xq    = base + O_XQ;
    float* agg   = base + O_AGG;
    float* g0    = base + O_G0;
    float* g1b   = g0 + (size_t)NN*128;
    float* xc    = base + O_XC;
    float* xq2   = base + O_XQ2;
    int*   perm  = (int*)(base + O_PERM);
    float* W1e   = base + O_W1E;

    static bool attr_done = false;
    if (!attr_done){
        cudaFuncSetAttribute(hop2_dense, cudaFuncAttributeMaxDynamicSharedMemorySize, 84480);
        cudaFuncSetAttribute(esm_agg,    cudaFuncAttributeMaxDynamicSharedMemorySize, 68096);
        cudaFuncSetAttribute(a2_dense,   cudaFuncAttributeMaxDynamicSharedMemorySize, 58336);
        attr_done = true;
    }

    const int EG = (NEC + 255)/256;
    const size_t S128 = (size_t)NN*128;

    // ---- graph prep ----
    prep0<<<32 + (4*384*256+255)/256, 256>>>((float4*)base, W1, W1e);
    edge_build<<<EG,256>>>(ei, ewt, deg, AT, CNT);

    // ---- x_q = hop(hop(x)) ----
    hop2_dense<<<BB,256,84480>>>(x, xq, AT, deg);

    // ---- attention pair (2 heads batched over blockIdx.z) ----
    auto attention_pair = [&](const float* kv, const float* q0, int pairbase){
        gemm_h3<<<dim3(2,64,2),256>>>(kv, Wk + (size_t)pairbase*128*128, q0, tx, h3);
        gemm64p<<<dim3(4,64,2),256>>>(h3, W1e + (size_t)pairbase*384*256, t1,
                                      256, 384, 1, (size_t)NN*384, (size_t)384*256, (size_t)NN*256);
        gemm_w2tail<<<dim3(2,64,2),256>>>(t1, W2 + (size_t)pairbase*256*128,
                                          W3 + (size_t)pairbase*128, lp);
    };

    attention_pair(x, xq, 0);

    // ---- dense edge softmax (+ f1/f2 softmax) + aggregation ----
    esm_agg<<<BB,256,68096>>>(CNT, lp, x, STg, agg);
    gemm64p<<<dim3(2,64,2),256>>>(agg, linW, g0, 128, 128, 0,
                                  0, (size_t)128*128, S128);
    xc_combine<<<2048,256>>>(x, g0, g1b, xc);

    // ---- second round ----
    hop2_dense<<<BB,256,84480>>>(xc, xq2, AT, deg);
    attention_pair(xc, xq2, 2);

    // ---- per-head softmax + score softmax + top-k + pooled outputs ----
    finalize<<<BB,256>>>(lp, x, perm, out);

    // ---- A2 = S_p^T (A_d S_p), dense per graph, direct write ----
    a2_dense<<<BB,256,58336>>>(AT, deg, STg, perm, out + OFF_A2);
}